// round 1
// baseline (speedup 1.0000x reference)
#include <cuda_runtime.h>

#define NN   100000
#define EE   1600000
#define DIN  128
#define HH   256
#define OUTD 20
#define EPSV 1e-5f

// ---------------- scratch (static device allocations; no cudaMalloc) ----------------
__device__ __align__(16) float g_tmp[(size_t)NN * HH];   // h @ W  (also holds N x 20 for last layer)
__device__ __align__(16) float g_agg[(size_t)NN * HH];   // aggregation accumulator
__device__ __align__(16) float g_h  [(size_t)NN * HH];   // layer activations
__device__ float g_deg [NN];
__device__ float g_dinv[NN];
__device__ float g_coef[EE];

// ---------------- degree / normalization ----------------
__global__ void k_zero_deg() {
    int i = blockIdx.x * blockDim.x + threadIdx.x;
    if (i < NN) g_deg[i] = 0.f;
}
__global__ void k_count(const int* __restrict__ dst) {
    int e = blockIdx.x * blockDim.x + threadIdx.x;
    if (e < EE) atomicAdd(&g_deg[dst[e]], 1.f);
}
__global__ void k_dinv() {
    int i = blockIdx.x * blockDim.x + threadIdx.x;
    if (i < NN) g_dinv[i] = rsqrtf(g_deg[i] + 1.f);   // deg includes self-loop
}
__global__ void k_coef(const int* __restrict__ src, const int* __restrict__ dst) {
    int e = blockIdx.x * blockDim.x + threadIdx.x;
    if (e < EE) g_coef[e] = g_dinv[src[e]] * g_dinv[dst[e]];
}

// ---------------- generic fp32 SGEMM: C[Nr,M] = A[Nr,K] @ B[K,M] ----------------
// 128x64 block tile, BK=16, 256 threads, 8x4 micro-tile per thread.
__global__ void k_sgemm(const float* __restrict__ A, const float* __restrict__ B,
                        float* __restrict__ C, int Nr, int K, int M) {
    __shared__ float As[16][128];
    __shared__ float Bs[16][64];
    const int tid = threadIdx.x;
    const int rowBase = blockIdx.y * 128;
    const int colBase = blockIdx.x * 64;
    const int tx = tid & 15;       // 0..15 -> 4 cols each
    const int ty = tid >> 4;       // 0..15 -> 8 rows each

    float acc[8][4];
#pragma unroll
    for (int i = 0; i < 8; i++)
#pragma unroll
        for (int j = 0; j < 4; j++) acc[i][j] = 0.f;

    for (int k0 = 0; k0 < K; k0 += 16) {
        // load A tile: 128x16 = 512 float4; 2 per thread
#pragma unroll
        for (int i = 0; i < 2; i++) {
            int idx = tid + i * 256;          // 0..511
            int m   = idx >> 2;               // tile row 0..127
            int kc  = (idx & 3) * 4;          // k offset 0,4,8,12
            int grow = rowBase + m;
            float4 a4 = make_float4(0.f, 0.f, 0.f, 0.f);
            if (grow < Nr)
                a4 = *reinterpret_cast<const float4*>(&A[(size_t)grow * K + k0 + kc]);
            As[kc + 0][m] = a4.x; As[kc + 1][m] = a4.y;
            As[kc + 2][m] = a4.z; As[kc + 3][m] = a4.w;
        }
        // load B tile: 16x64, 4 scalars per thread (guard col<M for M=20 case)
        {
            int r = tid >> 4;
            int cb = (tid & 15) * 4;
#pragma unroll
            for (int j = 0; j < 4; j++) {
                int col = colBase + cb + j;
                Bs[r][cb + j] = (col < M) ? B[(size_t)(k0 + r) * M + col] : 0.f;
            }
        }
        __syncthreads();
#pragma unroll
        for (int k = 0; k < 16; k++) {
            float a[8], b[4];
#pragma unroll
            for (int i = 0; i < 8; i++) a[i] = As[k][ty * 8 + i];
#pragma unroll
            for (int j = 0; j < 4; j++) b[j] = Bs[k][tx * 4 + j];
#pragma unroll
            for (int i = 0; i < 8; i++)
#pragma unroll
                for (int j = 0; j < 4; j++) acc[i][j] += a[i] * b[j];
        }
        __syncthreads();
    }

#pragma unroll
    for (int i = 0; i < 8; i++) {
        int row = rowBase + ty * 8 + i;
        if (row >= Nr) continue;
#pragma unroll
        for (int j = 0; j < 4; j++) {
            int col = colBase + tx * 4 + j;
            if (col < M) C[(size_t)row * M + col] = acc[i][j];
        }
    }
}

// ---------------- self-loop init: agg = tmp * dinv^2 ----------------
template <int LD4>   // row length in float4 units (64 for H=256, 5 for OUT=20)
__global__ void k_init_agg() {
    int idx = blockIdx.x * blockDim.x + threadIdx.x;
    const int total = NN * LD4;
    if (idx >= total) return;
    int node = idx / LD4;
    float d = g_dinv[node];
    float s = d * d;
    float4 v = reinterpret_cast<const float4*>(g_tmp)[idx];
    v.x *= s; v.y *= s; v.z *= s; v.w *= s;
    reinterpret_cast<float4*>(g_agg)[idx] = v;
}

// ---------------- edge scatter: agg[dst] += tmp[src] * coef ----------------
template <int LD4>
__global__ void k_scatter(const int* __restrict__ src, const int* __restrict__ dst) {
    int t = blockIdx.x * blockDim.x + threadIdx.x;
    const int total = EE * LD4;
    if (t >= total) return;
    int e = t / LD4;
    int g = t - e * LD4;
    float c = g_coef[e];
    int s = src[e];
    int d = dst[e];
    float4 v = reinterpret_cast<const float4*>(g_tmp)[s * LD4 + g];
    v.x *= c; v.y *= c; v.z *= c; v.w *= c;
    float* p = &g_agg[((size_t)d * LD4 + g) * 4];
    asm volatile("red.global.add.v4.f32 [%0], {%1,%2,%3,%4};"
                 :: "l"(p), "f"(v.x), "f"(v.y), "f"(v.z), "f"(v.w)
                 : "memory");
}

// ---------------- epilogue: h = relu(BN(agg + b)) ----------------
__global__ void k_bn_relu(const float* __restrict__ b,
                          const float* __restrict__ gamma,
                          const float* __restrict__ beta,
                          const float* __restrict__ mean,
                          const float* __restrict__ var) {
    int idx = blockIdx.x * blockDim.x + threadIdx.x;
    const int total = NN * (HH / 4);
    if (idx >= total) return;
    int c4 = idx & (HH / 4 - 1);     // HH/4 = 64, power of 2
    int c = c4 * 4;
    float4 v = reinterpret_cast<const float4*>(g_agg)[idx];
    float4 r;
    {
        float sc = rsqrtf(var[c + 0] + EPSV) * gamma[c + 0];
        r.x = fmaxf((v.x + b[c + 0] - mean[c + 0]) * sc + beta[c + 0], 0.f);
    }
    {
        float sc = rsqrtf(var[c + 1] + EPSV) * gamma[c + 1];
        r.y = fmaxf((v.y + b[c + 1] - mean[c + 1]) * sc + beta[c + 1], 0.f);
    }
    {
        float sc = rsqrtf(var[c + 2] + EPSV) * gamma[c + 2];
        r.z = fmaxf((v.z + b[c + 2] - mean[c + 2]) * sc + beta[c + 2], 0.f);
    }
    {
        float sc = rsqrtf(var[c + 3] + EPSV) * gamma[c + 3];
        r.w = fmaxf((v.w + b[c + 3] - mean[c + 3]) * sc + beta[c + 3], 0.f);
    }
    reinterpret_cast<float4*>(g_h)[idx] = r;
}

// ---------------- final: out = agg + b3 ----------------
__global__ void k_final(const float* __restrict__ b3, float* __restrict__ out) {
    int idx = blockIdx.x * blockDim.x + threadIdx.x;
    const int total = NN * (OUTD / 4);   // OUTD = 20 -> 5 float4 per row
    if (idx >= total) return;
    int c4 = idx % (OUTD / 4);
    float4 v = reinterpret_cast<const float4*>(g_agg)[idx];
    float4 bb = reinterpret_cast<const float4*>(b3)[c4];
    v.x += bb.x; v.y += bb.y; v.z += bb.z; v.w += bb.w;
    reinterpret_cast<float4*>(out)[idx] = v;
}

// ---------------- launcher ----------------
extern "C" void kernel_launch(void* const* d_in, const int* in_sizes, int n_in,
                              void* d_out, int out_size) {
    const float* x     = (const float*)d_in[0];
    const int*   ei    = (const int*)  d_in[1];
    const float* W0    = (const float*)d_in[2];
    const float* b0    = (const float*)d_in[3];
    const float* W1    = (const float*)d_in[4];
    const float* b1    = (const float*)d_in[5];
    const float* W2    = (const float*)d_in[6];
    const float* b2    = (const float*)d_in[7];
    const float* W3    = (const float*)d_in[8];
    const float* b3    = (const float*)d_in[9];
    const float* gamma = (const float*)d_in[10];
    const float* beta  = (const float*)d_in[11];
    const float* mean  = (const float*)d_in[12];
    const float* var   = (const float*)d_in[13];
    float* out = (float*)d_out;

    const int* src = ei;
    const int* dst = ei + EE;

    float *tmpP = nullptr, *hP = nullptr;
    cudaGetSymbolAddress((void**)&tmpP, g_tmp);
    cudaGetSymbolAddress((void**)&hP,   g_h);

    const int T = 256;
    // normalization precompute
    k_zero_deg<<<(NN + T - 1) / T, T>>>();
    k_count   <<<(EE + T - 1) / T, T>>>(dst);
    k_dinv    <<<(NN + T - 1) / T, T>>>();
    k_coef    <<<(EE + T - 1) / T, T>>>(src, dst);

    dim3 gH((HH + 63) / 64, (NN + 127) / 128);
    dim3 gO((OUTD + 63) / 64, (NN + 127) / 128);

    const int nElemH4 = NN * (HH / 4);        // 6.4M
    const int nEdgeH4 = EE * (HH / 4);        // 102.4M
    const int nElemO4 = NN * (OUTD / 4);      // 0.5M
    const int nEdgeO4 = EE * (OUTD / 4);      // 8M

    // layer 0: x[100k,128] @ W0[128,256]
    k_sgemm<<<gH, T>>>(x, W0, tmpP, NN, DIN, HH);
    k_init_agg<HH / 4><<<(nElemH4 + T - 1) / T, T>>>();
    k_scatter <HH / 4><<<(nEdgeH4 + T - 1) / T, T>>>(src, dst);
    k_bn_relu<<<(nElemH4 + T - 1) / T, T>>>(b0, gamma + 0 * HH, beta + 0 * HH,
                                            mean + 0 * HH, var + 0 * HH);
    // layer 1
    k_sgemm<<<gH, T>>>(hP, W1, tmpP, NN, HH, HH);
    k_init_agg<HH / 4><<<(nElemH4 + T - 1) / T, T>>>();
    k_scatter <HH / 4><<<(nEdgeH4 + T - 1) / T, T>>>(src, dst);
    k_bn_relu<<<(nElemH4 + T - 1) / T, T>>>(b1, gamma + 1 * HH, beta + 1 * HH,
                                            mean + 1 * HH, var + 1 * HH);
    // layer 2
    k_sgemm<<<gH, T>>>(hP, W2, tmpP, NN, HH, HH);
    k_init_agg<HH / 4><<<(nElemH4 + T - 1) / T, T>>>();
    k_scatter <HH / 4><<<(nEdgeH4 + T - 1) / T, T>>>(src, dst);
    k_bn_relu<<<(nElemH4 + T - 1) / T, T>>>(b2, gamma + 2 * HH, beta + 2 * HH,
                                            mean + 2 * HH, var + 2 * HH);
    // layer 3: h[100k,256] @ W3[256,20], then out = agg + b3
    k_sgemm<<<gO, T>>>(hP, W3, tmpP, NN, HH, OUTD);
    k_init_agg<OUTD / 4><<<(nElemO4 + T - 1) / T, T>>>();
    k_scatter <OUTD / 4><<<(nEdgeO4 + T - 1) / T, T>>>(src, dst);
    k_final<<<(nElemO4 + T - 1) / T, T>>>(b3, out);
}

// round 5
// speedup vs baseline: 1.1593x; 1.1593x over previous
#include <cuda_runtime.h>
#include <cuda_bf16.h>
#include <cstdint>

#define NN   100000
#define EE   1600000
#define DIN  128
#define HH   256
#define OUTD 20
#define OUTP 32
#define EPSV 1e-5f
#define NBLK ((NN + 127) / 128)   // 782

// ---------------- static device scratch ----------------
__device__ __align__(16) float g_agg[(size_t)NN * HH];
__device__ __align__(16) float g_tmp[(size_t)NN * HH];
__device__ __align__(16) __nv_bfloat16 g_ah [(size_t)NN * HH];
__device__ __align__(16) __nv_bfloat16 g_al [(size_t)NN * HH];
__device__ __align__(16) __nv_bfloat16 g_axh[(size_t)NN * DIN];
__device__ __align__(16) __nv_bfloat16 g_axl[(size_t)NN * DIN];
__device__ float g_deg [NN];
__device__ float g_dinv[NN];
__device__ float g_coef[EE];
__device__ __align__(16) __nv_bfloat16 g_w0h[HH * DIN],  g_w0l[HH * DIN];   // [256][128]  (Wt[n][k])
__device__ __align__(16) __nv_bfloat16 g_w1h[HH * HH],   g_w1l[HH * HH];
__device__ __align__(16) __nv_bfloat16 g_w2h[HH * HH],   g_w2l[HH * HH];
__device__ __align__(16) __nv_bfloat16 g_w3h[OUTP * HH], g_w3l[OUTP * HH];  // [32][256] padded

// ---------------- helpers ----------------
__device__ __forceinline__ uint32_t smem_u32(const void* p) {
    uint32_t a;
    asm("{ .reg .u64 t; cvta.to.shared.u64 t, %1; cvt.u32.u64 %0, t; }" : "=r"(a) : "l"(p));
    return a;
}
__device__ __forceinline__ void split2(float v, __nv_bfloat16& h, __nv_bfloat16& l) {
    h = __float2bfloat16(v);
    l = __float2bfloat16(v - __bfloat162float(h));
}
__device__ __forceinline__ void cp16(uint32_t dst, const void* src, uint32_t sz) {
    asm volatile("cp.async.cg.shared.global [%0], [%1], 16, %2;"
                 :: "r"(dst), "l"(src), "r"(sz) : "memory");
}
#define CP_COMMIT() asm volatile("cp.async.commit_group;" ::: "memory")
#define CP_WAIT(n)  asm volatile("cp.async.wait_group %0;" :: "n"(n) : "memory")

__device__ __forceinline__ void ldsm_x4(uint32_t* r, uint32_t a) {
    asm volatile("ldmatrix.sync.aligned.m8n8.x4.shared.b16 {%0,%1,%2,%3}, [%4];"
                 : "=r"(r[0]), "=r"(r[1]), "=r"(r[2]), "=r"(r[3]) : "r"(a));
}
__device__ __forceinline__ void ldsm_x2(uint32_t* r, uint32_t a) {
    asm volatile("ldmatrix.sync.aligned.m8n8.x2.shared.b16 {%0,%1}, [%2];"
                 : "=r"(r[0]), "=r"(r[1]) : "r"(a));
}
__device__ __forceinline__ void mma16816(float* c, const uint32_t* a, const uint32_t* b) {
    asm volatile("mma.sync.aligned.m16n8k16.row.col.f32.bf16.bf16.f32 "
                 "{%0,%1,%2,%3}, {%4,%5,%6,%7}, {%8,%9}, {%0,%1,%2,%3};"
                 : "+f"(c[0]), "+f"(c[1]), "+f"(c[2]), "+f"(c[3])
                 : "r"(a[0]), "r"(a[1]), "r"(a[2]), "r"(a[3]), "r"(b[0]), "r"(b[1]));
}
// swizzled byte offset inside a tile with 64-byte rows
__device__ __forceinline__ int swz(int r, int b) {
    return r * 64 + (b ^ (((r >> 1) & 3) << 4));
}

// ---------------- degree / normalization ----------------
__global__ void k_zero_deg() {
    int i = blockIdx.x * blockDim.x + threadIdx.x;
    if (i < NN) g_deg[i] = 0.f;
}
__global__ void k_count(const int* __restrict__ dst) {
    int e = blockIdx.x * blockDim.x + threadIdx.x;
    if (e < EE) atomicAdd(&g_deg[dst[e]], 1.f);
}
__global__ void k_dinv() {
    int i = blockIdx.x * blockDim.x + threadIdx.x;
    if (i < NN) g_dinv[i] = rsqrtf(g_deg[i] + 1.f);
}
__global__ void k_coef(const int* __restrict__ src, const int* __restrict__ dst) {
    int e = blockIdx.x * blockDim.x + threadIdx.x;
    if (e < EE) g_coef[e] = g_dinv[src[e]] * g_dinv[dst[e]];
}

// ---------------- weight transpose + bf16 split (+pad) ----------------
__global__ void k_wsplit(const float* __restrict__ W, __nv_bfloat16* __restrict__ oh,
                         __nv_bfloat16* __restrict__ ol, int K, int M, int Mpad) {
    int idx = blockIdx.x * blockDim.x + threadIdx.x;
    if (idx >= Mpad * K) return;
    int n = idx / K, k = idx - n * K;
    float v = (n < M) ? W[(size_t)k * M + n] : 0.f;
    __nv_bfloat16 h, l; split2(v, h, l);
    oh[idx] = h; ol[idx] = l;
}

// ---------------- elementwise fp32 -> bf16 split ----------------
__global__ void k_split(const float* __restrict__ in, __nv_bfloat16* __restrict__ oh,
                        __nv_bfloat16* __restrict__ ol, int total4) {
    int idx = blockIdx.x * blockDim.x + threadIdx.x;
    if (idx >= total4) return;
    float4 v = reinterpret_cast<const float4*>(in)[idx];
    __nv_bfloat16 h[4], l[4];
    split2(v.x, h[0], l[0]); split2(v.y, h[1], l[1]);
    split2(v.z, h[2], l[2]); split2(v.w, h[3], l[3]);
    *reinterpret_cast<uint2*>(oh + (size_t)idx * 4) = *reinterpret_cast<uint2*>(h);
    *reinterpret_cast<uint2*>(ol + (size_t)idx * 4) = *reinterpret_cast<uint2*>(l);
}

// ---------------- L0: agg_x init (self-loop) ----------------
__global__ void k_init_aggx(const float* __restrict__ x) {
    int idx = blockIdx.x * blockDim.x + threadIdx.x;
    if (idx >= NN * (DIN / 4)) return;
    int node = idx >> 5;                       // DIN/4 = 32
    float d = g_dinv[node]; float s = d * d;
    float4 v = reinterpret_cast<const float4*>(x)[idx];
    v.x *= s; v.y *= s; v.z *= s; v.w *= s;
    reinterpret_cast<float4*>(g_agg)[idx] = v;
}

// ---------------- edge scatter: agg[dst] += vals[src] * coef ----------------
template <int LD4>
__global__ void k_scatter(const float* __restrict__ vals, const int* __restrict__ src,
                          const int* __restrict__ dst, float* __restrict__ agg) {
    int t = blockIdx.x * blockDim.x + threadIdx.x;
    if (t >= EE * LD4) return;
    int e = t / LD4;
    int g = t - e * LD4;
    float c = g_coef[e];
    int s = src[e];
    int d = dst[e];
    float4 v = reinterpret_cast<const float4*>(vals)[(size_t)s * LD4 + g];
    v.x *= c; v.y *= c; v.z *= c; v.w *= c;
    float* p = agg + ((size_t)d * LD4 + g) * 4;
    asm volatile("red.global.add.v4.f32 [%0], {%1,%2,%3,%4};"
                 :: "l"(p), "f"(v.x), "f"(v.y), "f"(v.z), "f"(v.w) : "memory");
}

// ---------------- post-scatter: BN+ReLU + bf16 split ----------------
__global__ void k_bnconv(const float* __restrict__ b, const float* __restrict__ gam,
                         const float* __restrict__ bet, const float* __restrict__ mean,
                         const float* __restrict__ var) {
    int idx = blockIdx.x * blockDim.x + threadIdx.x;
    if (idx >= NN * (HH / 4)) return;
    int c = (idx & (HH / 4 - 1)) * 4;
    float4 v = reinterpret_cast<const float4*>(g_agg)[idx];
    float r[4] = {v.x, v.y, v.z, v.w};
    __nv_bfloat16 h[4], l[4];
#pragma unroll
    for (int i = 0; i < 4; i++) {
        float sc = rsqrtf(var[c + i] + EPSV) * gam[c + i];
        float o = (b[c + i] - mean[c + i]) * sc + bet[c + i];
        float vv = fmaxf(r[i] * sc + o, 0.f);
        split2(vv, h[i], l[i]);
    }
    *reinterpret_cast<uint2*>(g_ah + (size_t)idx * 4) = *reinterpret_cast<uint2*>(h);
    *reinterpret_cast<uint2*>(g_al + (size_t)idx * 4) = *reinterpret_cast<uint2*>(l);
}

// ---------------- final: out = agg(20-wide) + b3 ----------------
__global__ void k_final(const float* __restrict__ b3, float* __restrict__ out) {
    int idx = blockIdx.x * blockDim.x + threadIdx.x;
    if (idx >= NN * (OUTD / 4)) return;
    int c4 = idx % (OUTD / 4);
    float4 v = reinterpret_cast<const float4*>(g_agg)[idx];
    float4 bb = reinterpret_cast<const float4*>(b3)[c4];
    v.x += bb.x; v.y += bb.y; v.z += bb.z; v.w += bb.w;
    reinterpret_cast<float4*>(out)[idx] = v;
}

// ---------------- mma.sync split-bf16 GEMM ----------------
// C[NN, *] = A[NN, K_TOT] @ Wt^T, Wt stored [Ncols][K_TOT] bf16 (h/l pair).
// CTA tile: 128 rows x NTILE cols. 256 threads.
// EPI 0: outTmp = val (outw-wide), outAgg = val * dinv^2
// EPI 1: BN(val + bias) -> ReLU -> bf16 split -> outH/outL (256-wide)
template <int K_TOT, int NTILE, int EPI>
__global__ void __launch_bounds__(256)
k_gemm(const __nv_bfloat16* __restrict__ Ah, const __nv_bfloat16* __restrict__ Al,
       const __nv_bfloat16* __restrict__ Bh, const __nv_bfloat16* __restrict__ Bl,
       float* __restrict__ outTmp, float* __restrict__ outAgg, int outw,
       __nv_bfloat16* __restrict__ outH, __nv_bfloat16* __restrict__ outL,
       const float* __restrict__ bb, const float* __restrict__ gam,
       const float* __restrict__ bet, const float* __restrict__ mean,
       const float* __restrict__ var) {
    constexpr int KC    = 32;                    // k per chunk
    constexpr int NCH   = K_TOT / KC;
    constexpr int SA    = 128 * 64;              // 8192 B per A half (128 rows x 64B)
    constexpr int SB    = NTILE * 64;            // B half bytes
    constexpr int STAGE = 2 * SA + 2 * SB;
    constexpr int WM    = (NTILE == 128) ? 32 : 16;
    constexpr int WN    = (NTILE == 128) ? 64 : 32;
    constexpr int WARPS_N = NTILE / WN;          // 2 or 1
    constexpr int MT    = WM / 16;               // 2 or 1
    constexpr int NT    = WN / 8;                // 8 or 4

    extern __shared__ char smem[];
    const uint32_t sbase = smem_u32(smem);
    const int tid  = threadIdx.x;
    const int wid  = tid >> 5;
    const int lane = tid & 31;
    const int rowBase = blockIdx.y * 128;
    const int colBase = blockIdx.x * NTILE;
    const int warp_m  = wid / WARPS_N;
    const int warp_n  = wid % WARPS_N;

    float acc[MT][NT][4];
#pragma unroll
    for (int i = 0; i < MT; i++)
#pragma unroll
        for (int j = 0; j < NT; j++)
#pragma unroll
            for (int q = 0; q < 4; q++) acc[i][j][q] = 0.f;

    // ---- stage loader (cp.async) ----
    auto load_stage = [&](int s, int kc) {
        const uint32_t base = sbase + s * STAGE;
        // A: 128 rows x 4 chunks x {h,l} = 1024 x 16B
#pragma unroll
        for (int i = 0; i < 4; i++) {
            int u = tid + i * 256;
            int half = u >> 9;
            int v = u & 511;
            int r = v >> 2, c16 = v & 3;
            int grow = rowBase + r;
            const __nv_bfloat16* gp = (half ? Al : Ah);
            const __nv_bfloat16* srcp = gp + (size_t)(grow < NN ? grow : 0) * K_TOT + kc + c16 * 8;
            cp16(base + half * SA + swz(r, c16 * 16), srcp, (grow < NN) ? 16u : 0u);
        }
        // B: NTILE rows x 4 chunks x {h,l}
#pragma unroll
        for (int i = 0; i < (NTILE * 8) / 256; i++) {
            int u = tid + i * 256;
            int half = (u >= NTILE * 4) ? 1 : 0;
            int v = u - half * NTILE * 4;
            int r = v >> 2, c16 = v & 3;
            const __nv_bfloat16* gp = (half ? Bl : Bh);
            const __nv_bfloat16* srcp = gp + (size_t)(colBase + r) * K_TOT + kc + c16 * 8;
            cp16(base + 2 * SA + half * SB + swz(r, c16 * 16), srcp, 16u);
        }
    };

    load_stage(0, 0);
    CP_COMMIT();

    for (int ch = 0; ch < NCH; ch++) {
        if (ch + 1 < NCH) {
            load_stage((ch + 1) & 1, (ch + 1) * KC);
            CP_COMMIT();
            CP_WAIT(1);
        } else {
            CP_WAIT(0);
        }
        __syncthreads();

        const uint32_t base = sbase + (ch & 1) * STAGE;
#pragma unroll
        for (int ks = 0; ks < 2; ks++) {
            uint32_t ah[MT][4], al[MT][4];
            const int ab = ks * 32 + ((lane >> 4) << 4);     // byte within 64B row
#pragma unroll
            for (int i = 0; i < MT; i++) {
                int r = warp_m * WM + i * 16 + (lane & 15);
                ldsm_x4(ah[i], base + swz(r, ab));
                ldsm_x4(al[i], base + SA + swz(r, ab));
            }
            const int bbyte = ks * 32 + ((lane >> 3) & 1) * 16;
#pragma unroll
            for (int j = 0; j < NT; j++) {
                int r = warp_n * WN + j * 8 + (lane & 7);
                uint32_t bh[2], bl[2];
                ldsm_x2(bh, base + 2 * SA + swz(r, bbyte));
                ldsm_x2(bl, base + 2 * SA + SB + swz(r, bbyte));
#pragma unroll
                for (int i = 0; i < MT; i++) {
                    mma16816(acc[i][j], ah[i], bh);
                    mma16816(acc[i][j], ah[i], bl);
                    mma16816(acc[i][j], al[i], bh);
                }
            }
        }
        __syncthreads();
    }

    // ---- epilogue ----
    const int g  = lane >> 2;
    const int tg = lane & 3;
#pragma unroll
    for (int i = 0; i < MT; i++) {
        int r0 = rowBase + warp_m * WM + i * 16 + g;
        int r1 = r0 + 8;
        bool v0 = r0 < NN, v1 = r1 < NN;
        if (EPI == 0) {
            float d20 = 0.f, d21 = 0.f;
            if (v0) { float d = g_dinv[r0]; d20 = d * d; }
            if (v1) { float d = g_dinv[r1]; d21 = d * d; }
#pragma unroll
            for (int j = 0; j < NT; j++) {
                int col = colBase + warp_n * WN + j * 8 + 2 * tg;
                if (col >= outw) continue;
                if (v0) {
                    float2 t = make_float2(acc[i][j][0], acc[i][j][1]);
                    *reinterpret_cast<float2*>(outTmp + (size_t)r0 * outw + col) = t;
                    float2 a = make_float2(t.x * d20, t.y * d20);
                    *reinterpret_cast<float2*>(outAgg + (size_t)r0 * outw + col) = a;
                }
                if (v1) {
                    float2 t = make_float2(acc[i][j][2], acc[i][j][3]);
                    *reinterpret_cast<float2*>(outTmp + (size_t)r1 * outw + col) = t;
                    float2 a = make_float2(t.x * d21, t.y * d21);
                    *reinterpret_cast<float2*>(outAgg + (size_t)r1 * outw + col) = a;
                }
            }
        } else {
#pragma unroll
            for (int j = 0; j < NT; j++) {
                int col = colBase + warp_n * WN + j * 8 + 2 * tg;
                float sc0 = rsqrtf(var[col] + EPSV) * gam[col];
                float of0 = (bb[col] - mean[col]) * sc0 + bet[col];
                float sc1 = rsqrtf(var[col + 1] + EPSV) * gam[col + 1];
                float of1 = (bb[col + 1] - mean[col + 1]) * sc1 + bet[col + 1];
                if (v0) {
                    float x0 = fmaxf(acc[i][j][0] * sc0 + of0, 0.f);
                    float x1 = fmaxf(acc[i][j][1] * sc1 + of1, 0.f);
                    __nv_bfloat16 h[2], l[2];
                    split2(x0, h[0], l[0]); split2(x1, h[1], l[1]);
                    *reinterpret_cast<uint32_t*>(outH + (size_t)r0 * HH + col) = *reinterpret_cast<uint32_t*>(h);
                    *reinterpret_cast<uint32_t*>(outL + (size_t)r0 * HH + col) = *reinterpret_cast<uint32_t*>(l);
                }
                if (v1) {
                    float x0 = fmaxf(acc[i][j][2] * sc0 + of0, 0.f);
                    float x1 = fmaxf(acc[i][j][3] * sc1 + of1, 0.f);
                    __nv_bfloat16 h[2], l[2];
                    split2(x0, h[0], l[0]); split2(x1, h[1], l[1]);
                    *reinterpret_cast<uint32_t*>(outH + (size_t)r1 * HH + col) = *reinterpret_cast<uint32_t*>(h);
                    *reinterpret_cast<uint32_t*>(outL + (size_t)r1 * HH + col) = *reinterpret_cast<uint32_t*>(l);
                }
            }
        }
    }
}

// ---------------- launcher ----------------
extern "C" void kernel_launch(void* const* d_in, const int* in_sizes, int n_in,
                              void* d_out, int out_size) {
    const float* x     = (const float*)d_in[0];
    const int*   ei    = (const int*)  d_in[1];
    const float* W0    = (const float*)d_in[2];
    const float* b0    = (const float*)d_in[3];
    const float* W1    = (const float*)d_in[4];
    const float* b1    = (const float*)d_in[5];
    const float* W2    = (const float*)d_in[6];
    const float* b2    = (const float*)d_in[7];
    const float* W3    = (const float*)d_in[8];
    const float* b3    = (const float*)d_in[9];
    const float* gamma = (const float*)d_in[10];
    const float* beta  = (const float*)d_in[11];
    const float* mean  = (const float*)d_in[12];
    const float* var   = (const float*)d_in[13];
    float* out = (float*)d_out;
    const int* src = ei;
    const int* dst = ei + EE;

    float *tmpP, *aggP;
    __nv_bfloat16 *ahP, *alP, *axhP, *axlP;
    __nv_bfloat16 *w0h, *w0l, *w1h, *w1l, *w2h, *w2l, *w3h, *w3l;
    cudaGetSymbolAddress((void**)&tmpP, g_tmp);
    cudaGetSymbolAddress((void**)&aggP, g_agg);
    cudaGetSymbolAddress((void**)&ahP,  g_ah);
    cudaGetSymbolAddress((void**)&alP,  g_al);
    cudaGetSymbolAddress((void**)&axhP, g_axh);
    cudaGetSymbolAddress((void**)&axlP, g_axl);
    cudaGetSymbolAddress((void**)&w0h, g_w0h); cudaGetSymbolAddress((void**)&w0l, g_w0l);
    cudaGetSymbolAddress((void**)&w1h, g_w1h); cudaGetSymbolAddress((void**)&w1l, g_w1l);
    cudaGetSymbolAddress((void**)&w2h, g_w2h); cudaGetSymbolAddress((void**)&w2l, g_w2l);
    cudaGetSymbolAddress((void**)&w3h, g_w3h); cudaGetSymbolAddress((void**)&w3l, g_w3l);

    // dynamic smem: 2 stages x (2*8192 + 2*NTILE*64)
    const int SM128 = 2 * (2 * 8192 + 2 * 128 * 64);   // 65536
    const int SM32  = 2 * (2 * 8192 + 2 * 32 * 64);    // 40960
    cudaFuncSetAttribute(k_gemm<128, 128, 1>, cudaFuncAttributeMaxDynamicSharedMemorySize, SM128);
    cudaFuncSetAttribute(k_gemm<256, 128, 0>, cudaFuncAttributeMaxDynamicSharedMemorySize, SM128);
    cudaFuncSetAttribute(k_gemm<256, 32, 0>,  cudaFuncAttributeMaxDynamicSharedMemorySize, SM32);

    const int T = 256;
    // normalization precompute
    k_zero_deg<<<(NN + T - 1) / T, T>>>();
    k_count   <<<(EE + T - 1) / T, T>>>(dst);
    k_dinv    <<<(NN + T - 1) / T, T>>>();
    k_coef    <<<(EE + T - 1) / T, T>>>(src, dst);
    // weights: transpose + split (+pad for W3)
    k_wsplit<<<(HH * DIN + T - 1) / T, T>>>(W0, w0h, w0l, DIN, HH, HH);
    k_wsplit<<<(HH * HH  + T - 1) / T, T>>>(W1, w1h, w1l, HH, HH, HH);
    k_wsplit<<<(HH * HH  + T - 1) / T, T>>>(W2, w2h, w2l, HH, HH, HH);
    k_wsplit<<<(OUTP * HH + T - 1) / T, T>>>(W3, w3h, w3l, HH, OUTD, OUTP);

    // ---- layer 0: aggregate x first (128 cols), then GEMM with fused BN+ReLU+split
    k_init_aggx<<<(NN * 32 + T - 1) / T, T>>>(x);
    k_scatter<32><<<((size_t)EE * 32 + T - 1) / T, T>>>(x, src, dst, aggP);
    k_split<<<(NN * 32 + T - 1) / T, T>>>(aggP, axhP, axlP, NN * 32);
    k_gemm<128, 128, 1><<<dim3(2, NBLK), 256, SM128>>>(axhP, axlP, w0h, w0l,
        nullptr, nullptr, 0, ahP, alP, b0, gamma, beta, mean, var);

    // ---- layer 1
    k_gemm<256, 128, 0><<<dim3(2, NBLK), 256, SM128>>>(ahP, alP, w1h, w1l,
        tmpP, aggP, HH, nullptr, nullptr, nullptr, nullptr, nullptr, nullptr, nullptr);
    k_scatter<64><<<((size_t)EE * 64 + T - 1) / T, T>>>(tmpP, src, dst, aggP);
    k_bnconv<<<(NN * 64 + T - 1) / T, T>>>(b1, gamma + HH, beta + HH, mean + HH, var + HH);

    // ---- layer 2
    k_gemm<256, 128, 0><<<dim3(2, NBLK), 256, SM128>>>(ahP, alP, w2h, w2l,
        tmpP, aggP, HH, nullptr, nullptr, nullptr, nullptr, nullptr, nullptr, nullptr);
    k_scatter<64><<<((size_t)EE * 64 + T - 1) / T, T>>>(tmpP, src, dst, aggP);
    k_bnconv<<<(NN * 64 + T - 1) / T, T>>>(b2, gamma + 2 * HH, beta + 2 * HH, mean + 2 * HH, var + 2 * HH);

    // ---- layer 3: GEMM (N padded to 32, stores 20-wide), aggregate, add bias
    k_gemm<256, 32, 0><<<dim3(1, NBLK), 256, SM32>>>(ahP, alP, w3h, w3l,
        tmpP, aggP, OUTD, nullptr, nullptr, nullptr, nullptr, nullptr, nullptr, nullptr);
    k_scatter<5><<<((size_t)EE * 5 + T - 1) / T, T>>>(tmpP, src, dst, aggP);
    k_final<<<(NN * 5 + T - 1) / T, T>>>(b3, out);
}

// round 9
// speedup vs baseline: 2.7378x; 2.3617x over previous
#include <cuda_runtime.h>
#include <cuda_bf16.h>
#include <cstdint>

#define NN   100000
#define EE   1600000
#define DIN  128
#define HH   256
#define OUTD 20
#define OUTP 32
#define EPSV 1e-5f
#define NBLK ((NN + 127) / 128)   // 782

// ---------------- static device scratch ----------------
__device__ __align__(16) float g_tmp[(size_t)NN * HH];
__device__ __align__(16) __nv_bfloat16 g_ah [(size_t)NN * HH];
__device__ __align__(16) __nv_bfloat16 g_al [(size_t)NN * HH];
__device__ __align__(16) __nv_bfloat16 g_axh[(size_t)NN * DIN];
__device__ __align__(16) __nv_bfloat16 g_axl[(size_t)NN * DIN];
__device__ int   g_cnt[NN];
__device__ int   g_rowptr[NN + 1];
__device__ int   g_cursor[NN];
__device__ int   g_esrc[EE];
__device__ float g_ecoef[EE];
__device__ float g_dinv[NN];
__device__ __align__(16) __nv_bfloat16 g_w0h[HH * DIN],  g_w0l[HH * DIN];
__device__ __align__(16) __nv_bfloat16 g_w1h[HH * HH],   g_w1l[HH * HH];
__device__ __align__(16) __nv_bfloat16 g_w2h[HH * HH],   g_w2l[HH * HH];
__device__ __align__(16) __nv_bfloat16 g_w3h[OUTP * HH], g_w3l[OUTP * HH];

// ---------------- helpers ----------------
__device__ __forceinline__ uint32_t smem_u32(const void* p) {
    uint32_t a;
    asm("{ .reg .u64 t; cvta.to.shared.u64 t, %1; cvt.u32.u64 %0, t; }" : "=r"(a) : "l"(p));
    return a;
}
__device__ __forceinline__ void split2(float v, __nv_bfloat16& h, __nv_bfloat16& l) {
    h = __float2bfloat16(v);
    l = __float2bfloat16(v - __bfloat162float(h));
}
__device__ __forceinline__ void cp16(uint32_t dst, const void* src, uint32_t sz) {
    asm volatile("cp.async.cg.shared.global [%0], [%1], 16, %2;"
                 :: "r"(dst), "l"(src), "r"(sz) : "memory");
}
#define CP_COMMIT() asm volatile("cp.async.commit_group;" ::: "memory")
#define CP_WAIT(n)  asm volatile("cp.async.wait_group %0;" :: "n"(n) : "memory")

__device__ __forceinline__ void ldsm_x4(uint32_t* r, uint32_t a) {
    asm volatile("ldmatrix.sync.aligned.m8n8.x4.shared.b16 {%0,%1,%2,%3}, [%4];"
                 : "=r"(r[0]), "=r"(r[1]), "=r"(r[2]), "=r"(r[3]) : "r"(a));
}
__device__ __forceinline__ void ldsm_x2(uint32_t* r, uint32_t a) {
    asm volatile("ldmatrix.sync.aligned.m8n8.x2.shared.b16 {%0,%1}, [%2];"
                 : "=r"(r[0]), "=r"(r[1]) : "r"(a));
}
__device__ __forceinline__ void mma16816(float* c, const uint32_t* a, const uint32_t* b) {
    asm volatile("mma.sync.aligned.m16n8k16.row.col.f32.bf16.bf16.f32 "
                 "{%0,%1,%2,%3}, {%4,%5,%6,%7}, {%8,%9}, {%0,%1,%2,%3};"
                 : "+f"(c[0]), "+f"(c[1]), "+f"(c[2]), "+f"(c[3])
                 : "r"(a[0]), "r"(a[1]), "r"(a[2]), "r"(a[3]), "r"(b[0]), "r"(b[1]));
}
__device__ __forceinline__ int swz(int r, int b) {
    return r * 64 + (b ^ (((r >> 1) & 3) << 4));
}

// ---------------- CSR build ----------------
__global__ void k_zero_cnt() {
    int i = blockIdx.x * blockDim.x + threadIdx.x;
    if (i < NN) g_cnt[i] = 0;
}
__global__ void k_count(const int* __restrict__ dst) {
    int e = blockIdx.x * blockDim.x + threadIdx.x;
    if (e < EE) atomicAdd(&g_cnt[dst[e]], 1);
}
// single-CTA two-level exclusive scan; also emits dinv and cursor
__global__ void k_scan() {
    __shared__ int sums[1024];
    const int t = threadIdx.x;
    const int CH = (NN + 1023) / 1024;           // 98
    int beg = t * CH;
    int end = beg + CH; if (end > NN) end = NN;
    if (beg > NN) beg = NN;
    int s = 0;
    for (int i = beg; i < end; i++) s += g_cnt[i];
    sums[t] = s;
    __syncthreads();
    for (int off = 1; off < 1024; off <<= 1) {
        int add = (t >= off) ? sums[t - off] : 0;
        int v = sums[t];
        __syncthreads();
        sums[t] = v + add;
        __syncthreads();
    }
    int run = (t > 0) ? sums[t - 1] : 0;
    for (int i = beg; i < end; i++) {
        int c = g_cnt[i];
        g_rowptr[i] = run;
        g_cursor[i] = run;
        g_dinv[i]   = rsqrtf((float)c + 1.f);
        run += c;
    }
    if (t == 1023) g_rowptr[NN] = sums[1023];
}
__global__ void k_fill(const int* __restrict__ src, const int* __restrict__ dst) {
    int e = blockIdx.x * blockDim.x + threadIdx.x;
    if (e >= EE) return;
    int s = src[e], d = dst[e];
    int pos = atomicAdd(&g_cursor[d], 1);
    g_esrc[pos]  = s;
    g_ecoef[pos] = g_dinv[s] * g_dinv[d];
}

// ---------------- weight transpose + bf16 split (+pad) ----------------
__global__ void k_wsplit(const float* __restrict__ W, __nv_bfloat16* __restrict__ oh,
                         __nv_bfloat16* __restrict__ ol, int K, int M, int Mpad) {
    int idx = blockIdx.x * blockDim.x + threadIdx.x;
    if (idx >= Mpad * K) return;
    int n = idx / K, k = idx - n * K;
    float v = (n < M) ? W[(size_t)k * M + n] : 0.f;
    __nv_bfloat16 h, l; split2(v, h, l);
    oh[idx] = h; ol[idx] = l;
}

// ---------------- CSR gather aggregation, fused epilogues ----------------
// agg_row(n) = vals[n]*dinv[n]^2 + sum_j vals[esrc[j]] * ecoef[j]
// EPI 0: bf16 split -> outH/outL (width LD4*4)
// EPI 1: BN+ReLU (params) + bf16 split -> outH/outL (width 256)
// EPI 2: + bias -> outF (width outw=20, t<5)
template <int LD4, int GROUP, int EPI>
__global__ void __launch_bounds__(256)
k_gather(const float* __restrict__ vals,
         __nv_bfloat16* __restrict__ outH, __nv_bfloat16* __restrict__ outL,
         float* __restrict__ outF, int outw,
         const float* __restrict__ bb, const float* __restrict__ gam,
         const float* __restrict__ bet, const float* __restrict__ mean,
         const float* __restrict__ var) {
    const int gid = (blockIdx.x * 256 + threadIdx.x) / GROUP;
    const int t   = threadIdx.x % GROUP;
    if (gid >= NN) return;
    const bool act = (t < LD4);
    const int beg = g_rowptr[gid];
    const int end = g_rowptr[gid + 1];

    float4 acc = make_float4(0.f, 0.f, 0.f, 0.f);
    if (act) {
        float dv = g_dinv[gid];
        float d2 = dv * dv;
        float4 v = reinterpret_cast<const float4*>(vals)[(size_t)gid * LD4 + t];
        acc.x = v.x * d2; acc.y = v.y * d2; acc.z = v.z * d2; acc.w = v.w * d2;
    }
#pragma unroll 2
    for (int j = beg; j < end; j++) {
        int s   = __ldg(&g_esrc[j]);
        float c = __ldg(&g_ecoef[j]);
        if (act) {
            float4 v = reinterpret_cast<const float4*>(vals)[(size_t)s * LD4 + t];
            acc.x += v.x * c; acc.y += v.y * c; acc.z += v.z * c; acc.w += v.w * c;
        }
    }
    if (!act) return;

    if (EPI == 0) {
        __nv_bfloat16 h[4], l[4];
        split2(acc.x, h[0], l[0]); split2(acc.y, h[1], l[1]);
        split2(acc.z, h[2], l[2]); split2(acc.w, h[3], l[3]);
        size_t go = (size_t)gid * (LD4 * 4) + t * 4;
        *reinterpret_cast<uint2*>(outH + go) = *reinterpret_cast<uint2*>(h);
        *reinterpret_cast<uint2*>(outL + go) = *reinterpret_cast<uint2*>(l);
    } else if (EPI == 1) {
        int c0 = t * 4;
        float a[4] = {acc.x, acc.y, acc.z, acc.w};
        __nv_bfloat16 h[4], l[4];
#pragma unroll
        for (int i = 0; i < 4; i++) {
            float sc = rsqrtf(var[c0 + i] + EPSV) * gam[c0 + i];
            float of = (bb[c0 + i] - mean[c0 + i]) * sc + bet[c0 + i];
            float vv = fmaxf(a[i] * sc + of, 0.f);
            split2(vv, h[i], l[i]);
        }
        size_t go = (size_t)gid * HH + c0;
        *reinterpret_cast<uint2*>(outH + go) = *reinterpret_cast<uint2*>(h);
        *reinterpret_cast<uint2*>(outL + go) = *reinterpret_cast<uint2*>(l);
    } else {
        int c0 = t * 4;
        float4 b4 = *reinterpret_cast<const float4*>(bb + c0);
        acc.x += b4.x; acc.y += b4.y; acc.z += b4.z; acc.w += b4.w;
        *reinterpret_cast<float4*>(outF + (size_t)gid * outw + c0) = acc;
    }
}

// ---------------- mma.sync split-bf16 GEMM ----------------
// EPI 0: outTmp = val (outw-wide)
// EPI 1: BN(val + bias) -> ReLU -> bf16 split -> outH/outL (256-wide)
template <int K_TOT, int NTILE, int EPI>
__global__ void __launch_bounds__(256)
k_gemm(const __nv_bfloat16* __restrict__ Ah, const __nv_bfloat16* __restrict__ Al,
       const __nv_bfloat16* __restrict__ Bh, const __nv_bfloat16* __restrict__ Bl,
       float* __restrict__ outTmp, int outw,
       __nv_bfloat16* __restrict__ outH, __nv_bfloat16* __restrict__ outL,
       const float* __restrict__ bb, const float* __restrict__ gam,
       const float* __restrict__ bet, const float* __restrict__ mean,
       const float* __restrict__ var) {
    constexpr int KC    = 32;
    constexpr int NCH   = K_TOT / KC;
    constexpr int SA    = 128 * 64;
    constexpr int SB    = NTILE * 64;
    constexpr int STAGE = 2 * SA + 2 * SB;
    constexpr int WM    = (NTILE == 128) ? 32 : 16;
    constexpr int WN    = (NTILE == 128) ? 64 : 32;
    constexpr int WARPS_N = NTILE / WN;
    constexpr int MT    = WM / 16;
    constexpr int NT    = WN / 8;

    extern __shared__ char smem[];
    const uint32_t sbase = smem_u32(smem);
    const int tid  = threadIdx.x;
    const int wid  = tid >> 5;
    const int lane = tid & 31;
    const int rowBase = blockIdx.y * 128;
    const int colBase = blockIdx.x * NTILE;
    const int warp_m  = wid / WARPS_N;
    const int warp_n  = wid % WARPS_N;

    float acc[MT][NT][4];
#pragma unroll
    for (int i = 0; i < MT; i++)
#pragma unroll
        for (int j = 0; j < NT; j++)
#pragma unroll
            for (int q = 0; q < 4; q++) acc[i][j][q] = 0.f;

    auto load_stage = [&](int s, int kc) {
        const uint32_t base = sbase + s * STAGE;
#pragma unroll
        for (int i = 0; i < 4; i++) {
            int u = tid + i * 256;
            int half = u >> 9;
            int v = u & 511;
            int r = v >> 2, c16 = v & 3;
            int grow = rowBase + r;
            const __nv_bfloat16* gp = (half ? Al : Ah);
            const __nv_bfloat16* srcp = gp + (size_t)(grow < NN ? grow : 0) * K_TOT + kc + c16 * 8;
            cp16(base + half * SA + swz(r, c16 * 16), srcp, (grow < NN) ? 16u : 0u);
        }
#pragma unroll
        for (int i = 0; i < (NTILE * 8) / 256; i++) {
            int u = tid + i * 256;
            int half = (u >= NTILE * 4) ? 1 : 0;
            int v = u - half * NTILE * 4;
            int r = v >> 2, c16 = v & 3;
            const __nv_bfloat16* gp = (half ? Bl : Bh);
            const __nv_bfloat16* srcp = gp + (size_t)(colBase + r) * K_TOT + kc + c16 * 8;
            cp16(base + 2 * SA + half * SB + swz(r, c16 * 16), srcp, 16u);
        }
    };

    load_stage(0, 0);
    CP_COMMIT();

    for (int ch = 0; ch < NCH; ch++) {
        if (ch + 1 < NCH) {
            load_stage((ch + 1) & 1, (ch + 1) * KC);
            CP_COMMIT();
            CP_WAIT(1);
        } else {
            CP_WAIT(0);
        }
        __syncthreads();

        const uint32_t base = sbase + (ch & 1) * STAGE;
#pragma unroll
        for (int ks = 0; ks < 2; ks++) {
            uint32_t ah[MT][4], al[MT][4];
            const int ab = ks * 32 + ((lane >> 4) << 4);
#pragma unroll
            for (int i = 0; i < MT; i++) {
                int r = warp_m * WM + i * 16 + (lane & 15);
                ldsm_x4(ah[i], base + swz(r, ab));
                ldsm_x4(al[i], base + SA + swz(r, ab));
            }
            const int bbyte = ks * 32 + ((lane >> 3) & 1) * 16;
#pragma unroll
            for (int j = 0; j < NT; j++) {
                int r = warp_n * WN + j * 8 + (lane & 7);
                uint32_t bh[2], bl[2];
                ldsm_x2(bh, base + 2 * SA + swz(r, bbyte));
                ldsm_x2(bl, base + 2 * SA + SB + swz(r, bbyte));
#pragma unroll
                for (int i = 0; i < MT; i++) {
                    mma16816(acc[i][j], ah[i], bh);
                    mma16816(acc[i][j], ah[i], bl);
                    mma16816(acc[i][j], al[i], bh);
                }
            }
        }
        __syncthreads();
    }

    const int g  = lane >> 2;
    const int tg = lane & 3;
#pragma unroll
    for (int i = 0; i < MT; i++) {
        int r0 = rowBase + warp_m * WM + i * 16 + g;
        int r1 = r0 + 8;
        bool v0 = r0 < NN, v1 = r1 < NN;
        if (EPI == 0) {
#pragma unroll
            for (int j = 0; j < NT; j++) {
                int col = colBase + warp_n * WN + j * 8 + 2 * tg;
                if (col >= outw) continue;
                if (v0) {
                    float2 tv = make_float2(acc[i][j][0], acc[i][j][1]);
                    *reinterpret_cast<float2*>(outTmp + (size_t)r0 * outw + col) = tv;
                }
                if (v1) {
                    float2 tv = make_float2(acc[i][j][2], acc[i][j][3]);
                    *reinterpret_cast<float2*>(outTmp + (size_t)r1 * outw + col) = tv;
                }
            }
        } else {
#pragma unroll
            for (int j = 0; j < NT; j++) {
                int col = colBase + warp_n * WN + j * 8 + 2 * tg;
                float sc0 = rsqrtf(var[col] + EPSV) * gam[col];
                float of0 = (bb[col] - mean[col]) * sc0 + bet[col];
                float sc1 = rsqrtf(var[col + 1] + EPSV) * gam[col + 1];
                float of1 = (bb[col + 1] - mean[col + 1]) * sc1 + bet[col + 1];
                if (v0) {
                    float x0 = fmaxf(acc[i][j][0] * sc0 + of0, 0.f);
                    float x1 = fmaxf(acc[i][j][1] * sc1 + of1, 0.f);
                    __nv_bfloat16 h[2], l[2];
                    split2(x0, h[0], l[0]); split2(x1, h[1], l[1]);
                    *reinterpret_cast<uint32_t*>(outH + (size_t)r0 * HH + col) = *reinterpret_cast<uint32_t*>(h);
                    *reinterpret_cast<uint32_t*>(outL + (size_t)r0 * HH + col) = *reinterpret_cast<uint32_t*>(l);
                }
                if (v1) {
                    float x0 = fmaxf(acc[i][j][2] * sc0 + of0, 0.f);
                    float x1 = fmaxf(acc[i][j][3] * sc1 + of1, 0.f);
                    __nv_bfloat16 h[2], l[2];
                    split2(x0, h[0], l[0]); split2(x1, h[1], l[1]);
                    *reinterpret_cast<uint32_t*>(outH + (size_t)r1 * HH + col) = *reinterpret_cast<uint32_t*>(h);
                    *reinterpret_cast<uint32_t*>(outL + (size_t)r1 * HH + col) = *reinterpret_cast<uint32_t*>(l);
                }
            }
        }
    }
}

// ---------------- launcher ----------------
extern "C" void kernel_launch(void* const* d_in, const int* in_sizes, int n_in,
                              void* d_out, int out_size) {
    const float* x     = (const float*)d_in[0];
    const int*   ei    = (const int*)  d_in[1];
    const float* W0    = (const float*)d_in[2];
    const float* b0    = (const float*)d_in[3];
    const float* W1    = (const float*)d_in[4];
    const float* b1    = (const float*)d_in[5];
    const float* W2    = (const float*)d_in[6];
    const float* b2    = (const float*)d_in[7];
    const float* W3    = (const float*)d_in[8];
    const float* b3    = (const float*)d_in[9];
    const float* gamma = (const float*)d_in[10];
    const float* beta  = (const float*)d_in[11];
    const float* mean  = (const float*)d_in[12];
    const float* var   = (const float*)d_in[13];
    float* out = (float*)d_out;
    const int* src = ei;
    const int* dst = ei + EE;

    float* tmpP;
    __nv_bfloat16 *ahP, *alP, *axhP, *axlP;
    __nv_bfloat16 *w0h, *w0l, *w1h, *w1l, *w2h, *w2l, *w3h, *w3l;
    cudaGetSymbolAddress((void**)&tmpP, g_tmp);
    cudaGetSymbolAddress((void**)&ahP,  g_ah);
    cudaGetSymbolAddress((void**)&alP,  g_al);
    cudaGetSymbolAddress((void**)&axhP, g_axh);
    cudaGetSymbolAddress((void**)&axlP, g_axl);
    cudaGetSymbolAddress((void**)&w0h, g_w0h); cudaGetSymbolAddress((void**)&w0l, g_w0l);
    cudaGetSymbolAddress((void**)&w1h, g_w1h); cudaGetSymbolAddress((void**)&w1l, g_w1l);
    cudaGetSymbolAddress((void**)&w2h, g_w2h); cudaGetSymbolAddress((void**)&w2l, g_w2l);
    cudaGetSymbolAddress((void**)&w3h, g_w3h); cudaGetSymbolAddress((void**)&w3l, g_w3l);

    const int SM128 = 2 * (2 * 8192 + 2 * 128 * 64);   // 65536
    const int SM32  = 2 * (2 * 8192 + 2 * 32 * 64);    // 40960
    cudaFuncSetAttribute(k_gemm<128, 128, 1>, cudaFuncAttributeMaxDynamicSharedMemorySize, SM128);
    cudaFuncSetAttribute(k_gemm<256, 128, 0>, cudaFuncAttributeMaxDynamicSharedMemorySize, SM128);
    cudaFuncSetAttribute(k_gemm<256, 32, 0>,  cudaFuncAttributeMaxDynamicSharedMemorySize, SM32);

    const int T = 256;
    // CSR build
    k_zero_cnt<<<(NN + T - 1) / T, T>>>();
    k_count   <<<(EE + T - 1) / T, T>>>(dst);
    k_scan    <<<1, 1024>>>();
    k_fill    <<<(EE + T - 1) / T, T>>>(src, dst);
    // weights: transpose + split (+pad for W3)
    k_wsplit<<<(HH * DIN + T - 1) / T, T>>>(W0, w0h, w0l, DIN, HH, HH);
    k_wsplit<<<(HH * HH  + T - 1) / T, T>>>(W1, w1h, w1l, HH, HH, HH);
    k_wsplit<<<(HH * HH  + T - 1) / T, T>>>(W2, w2h, w2l, HH, HH, HH);
    k_wsplit<<<(OUTP * HH + T - 1) / T, T>>>(W3, w3h, w3l, HH, OUTD, OUTP);

    // ---- layer 0: aggregate x (128 cols) with fused bf16 split, then GEMM+BN+ReLU+split
    k_gather<32, 32, 0><<<(NN * 32 + 255) / 256, 256>>>(x, axhP, axlP,
        nullptr, 0, nullptr, nullptr, nullptr, nullptr, nullptr);
    k_gemm<128, 128, 1><<<dim3(2, NBLK), 256, SM128>>>(axhP, axlP, w0h, w0l,
        nullptr, 0, ahP, alP, b0, gamma, beta, mean, var);

    // ---- layer 1
    k_gemm<256, 128, 0><<<dim3(2, NBLK), 256, SM128>>>(ahP, alP, w1h, w1l,
        tmpP, HH, nullptr, nullptr, nullptr, nullptr, nullptr, nullptr, nullptr);
    k_gather<64, 64, 1><<<(NN * 64 + 255) / 256, 256>>>(tmpP, ahP, alP,
        nullptr, 0, b1, gamma + HH, beta + HH, mean + HH, var + HH);

    // ---- layer 2
    k_gemm<256, 128, 0><<<dim3(2, NBLK), 256, SM128>>>(ahP, alP, w2h, w2l,
        tmpP, HH, nullptr, nullptr, nullptr, nullptr, nullptr, nullptr, nullptr);
    k_gather<64, 64, 1><<<(NN * 64 + 255) / 256, 256>>>(tmpP, ahP, alP,
        nullptr, 0, b2, gamma + 2 * HH, beta + 2 * HH, mean + 2 * HH, var + 2 * HH);

    // ---- layer 3: GEMM (20-wide out), aggregate + bias -> out
    k_gemm<256, 32, 0><<<dim3(1, NBLK), 256, SM32>>>(ahP, alP, w3h, w3l,
        tmpP, OUTD, nullptr, nullptr, nullptr, nullptr, nullptr, nullptr, nullptr);
    k_gather<5, 8, 2><<<(NN * 8 + 255) / 256, 256>>>(tmpP, nullptr, nullptr,
        out, OUTD, b3, nullptr, nullptr, nullptr, nullptr);
}

// round 13
// speedup vs baseline: 2.7870x; 1.0180x over previous
#include <cuda_runtime.h>
#include <cuda_bf16.h>
#include <cstdint>

#define NN   100000
#define EE   1600000
#define DIN  128
#define HH   256
#define OUTD 20
#define OUTP 32
#define EPSV 1e-5f
#define NBLK ((NN + 127) / 128)   // 782

// ---------------- static device scratch ----------------
__device__ __align__(16) float g_tmp[(size_t)NN * HH];
__device__ __align__(16) __nv_bfloat16 g_ah [(size_t)NN * HH];
__device__ __align__(16) __nv_bfloat16 g_al [(size_t)NN * HH];
__device__ __align__(16) __nv_bfloat16 g_axh[(size_t)NN * DIN];
__device__ __align__(16) __nv_bfloat16 g_axl[(size_t)NN * DIN];
__device__ int   g_cnt[NN];
__device__ int   g_rowptr[NN + 1];
__device__ int   g_cursor[NN];
__device__ __align__(8) int2 g_edge[EE];     // {src, coef bits}
__device__ float g_dinv[NN];
__device__ __align__(16) __nv_bfloat16 g_w0h[HH * DIN],  g_w0l[HH * DIN];
__device__ __align__(16) __nv_bfloat16 g_w1h[HH * HH],   g_w1l[HH * HH];
__device__ __align__(16) __nv_bfloat16 g_w2h[HH * HH],   g_w2l[HH * HH];
__device__ __align__(16) __nv_bfloat16 g_w3h[OUTP * HH], g_w3l[OUTP * HH];

// ---------------- helpers ----------------
__device__ __forceinline__ uint32_t smem_u32(const void* p) {
    uint32_t a;
    asm("{ .reg .u64 t; cvta.to.shared.u64 t, %1; cvt.u32.u64 %0, t; }" : "=r"(a) : "l"(p));
    return a;
}
__device__ __forceinline__ void split2(float v, __nv_bfloat16& h, __nv_bfloat16& l) {
    h = __float2bfloat16(v);
    l = __float2bfloat16(v - __bfloat162float(h));
}
__device__ __forceinline__ void cp16(uint32_t dst, const void* src, uint32_t sz) {
    asm volatile("cp.async.cg.shared.global [%0], [%1], 16, %2;"
                 :: "r"(dst), "l"(src), "r"(sz) : "memory");
}
#define CP_COMMIT() asm volatile("cp.async.commit_group;" ::: "memory")
#define CP_WAIT(n)  asm volatile("cp.async.wait_group %0;" :: "n"(n) : "memory")

__device__ __forceinline__ void ldsm_x4(uint32_t* r, uint32_t a) {
    asm volatile("ldmatrix.sync.aligned.m8n8.x4.shared.b16 {%0,%1,%2,%3}, [%4];"
                 : "=r"(r[0]), "=r"(r[1]), "=r"(r[2]), "=r"(r[3]) : "r"(a));
}
__device__ __forceinline__ void ldsm_x2(uint32_t* r, uint32_t a) {
    asm volatile("ldmatrix.sync.aligned.m8n8.x2.shared.b16 {%0,%1}, [%2];"
                 : "=r"(r[0]), "=r"(r[1]) : "r"(a));
}
__device__ __forceinline__ void mma16816(float* c, const uint32_t* a, const uint32_t* b) {
    asm volatile("mma.sync.aligned.m16n8k16.row.col.f32.bf16.bf16.f32 "
                 "{%0,%1,%2,%3}, {%4,%5,%6,%7}, {%8,%9}, {%0,%1,%2,%3};"
                 : "+f"(c[0]), "+f"(c[1]), "+f"(c[2]), "+f"(c[3])
                 : "r"(a[0]), "r"(a[1]), "r"(a[2]), "r"(a[3]), "r"(b[0]), "r"(b[1]));
}
__device__ __forceinline__ int swz(int r, int b) {
    return r * 64 + (b ^ (((r >> 1) & 3) << 4));
}

// ---------------- CSR build ----------------
__global__ void k_zero_cnt() {
    int i = blockIdx.x * blockDim.x + threadIdx.x;
    if (i < NN) g_cnt[i] = 0;
}
__global__ void k_count(const int* __restrict__ dst) {
    int e = blockIdx.x * blockDim.x + threadIdx.x;
    if (e < EE) atomicAdd(&g_cnt[dst[e]], 1);
}
// single-CTA two-level exclusive scan; also emits dinv and cursor
__global__ void k_scan() {
    __shared__ int sums[1024];
    const int t = threadIdx.x;
    const int CH = (NN + 1023) / 1024;           // 98
    int beg = t * CH;
    int end = beg + CH; if (end > NN) end = NN;
    if (beg > NN) beg = NN;
    int s = 0;
    for (int i = beg; i < end; i++) s += g_cnt[i];
    sums[t] = s;
    __syncthreads();
    for (int off = 1; off < 1024; off <<= 1) {
        int add = (t >= off) ? sums[t - off] : 0;
        int v = sums[t];
        __syncthreads();
        sums[t] = v + add;
        __syncthreads();
    }
    int run = (t > 0) ? sums[t - 1] : 0;
    for (int i = beg; i < end; i++) {
        int c = g_cnt[i];
        g_rowptr[i] = run;
        g_cursor[i] = run;
        g_dinv[i]   = rsqrtf((float)c + 1.f);
        run += c;
    }
    if (t == 1023) g_rowptr[NN] = sums[1023];
}
__global__ void k_fill(const int* __restrict__ src, const int* __restrict__ dst) {
    int e = blockIdx.x * blockDim.x + threadIdx.x;
    if (e >= EE) return;
    int s = src[e], d = dst[e];
    int pos = atomicAdd(&g_cursor[d], 1);
    g_edge[pos] = make_int2(s, __float_as_int(g_dinv[s] * g_dinv[d]));
}

// ---------------- weight transpose + bf16 split (+pad) ----------------
__global__ void k_wsplit(const float* __restrict__ W, __nv_bfloat16* __restrict__ oh,
                         __nv_bfloat16* __restrict__ ol, int K, int M, int Mpad) {
    int idx = blockIdx.x * blockDim.x + threadIdx.x;
    if (idx >= Mpad * K) return;
    int n = idx / K, k = idx - n * K;
    float v = (n < M) ? W[(size_t)k * M + n] : 0.f;
    __nv_bfloat16 h, l; split2(v, h, l);
    oh[idx] = h; ol[idx] = l;
}

// ---------------- CSR gather aggregation, fused epilogues ----------------
// agg_row(n) = vals[n]*dinv[n]^2 + sum_j vals[e.src] * e.coef
// EPI 0: bf16 split -> outH/outL (width LD4*4)
// EPI 1: BN+ReLU (params) + bf16 split -> outH/outL (width 256)
// EPI 2: + bias -> outF (width outw=20, t<5)
template <int LD4, int GROUP, int EPI>
__global__ void __launch_bounds__(256)
k_gather(const float* __restrict__ vals,
         __nv_bfloat16* __restrict__ outH, __nv_bfloat16* __restrict__ outL,
         float* __restrict__ outF, int outw,
         const float* __restrict__ bb, const float* __restrict__ gam,
         const float* __restrict__ bet, const float* __restrict__ mean,
         const float* __restrict__ var) {
    const int gid = (blockIdx.x * 256 + threadIdx.x) / GROUP;
    const int t   = threadIdx.x % GROUP;
    if (gid >= NN) return;
    const bool act = (t < LD4);
    const int beg = __ldg(&g_rowptr[gid]);
    const int end = __ldg(&g_rowptr[gid + 1]);
    const float4* __restrict__ v4 = reinterpret_cast<const float4*>(vals);

    // dual accumulators: break the FFMA dependence chain, 2 loads in flight
    float4 acc0 = make_float4(0.f, 0.f, 0.f, 0.f);
    float4 acc1 = make_float4(0.f, 0.f, 0.f, 0.f);
    if (act) {
        float dv = g_dinv[gid];
        float d2 = dv * dv;
        float4 v = v4[(size_t)gid * LD4 + t];
        acc0.x = v.x * d2; acc0.y = v.y * d2; acc0.z = v.z * d2; acc0.w = v.w * d2;
    }
    int j = beg;
#pragma unroll 2
    for (; j + 1 < end; j += 2) {
        int2 e0 = __ldg(&g_edge[j]);
        int2 e1 = __ldg(&g_edge[j + 1]);
        if (act) {
            float4 u0 = v4[(size_t)e0.x * LD4 + t];
            float4 u1 = v4[(size_t)e1.x * LD4 + t];
            float c0 = __int_as_float(e0.y);
            float c1 = __int_as_float(e1.y);
            acc0.x += u0.x * c0; acc0.y += u0.y * c0; acc0.z += u0.z * c0; acc0.w += u0.w * c0;
            acc1.x += u1.x * c1; acc1.y += u1.y * c1; acc1.z += u1.z * c1; acc1.w += u1.w * c1;
        }
    }
    if (j < end) {
        int2 e0 = __ldg(&g_edge[j]);
        if (act) {
            float4 u0 = v4[(size_t)e0.x * LD4 + t];
            float c0 = __int_as_float(e0.y);
            acc0.x += u0.x * c0; acc0.y += u0.y * c0; acc0.z += u0.z * c0; acc0.w += u0.w * c0;
        }
    }
    if (!act) return;
    float4 acc = make_float4(acc0.x + acc1.x, acc0.y + acc1.y,
                             acc0.z + acc1.z, acc0.w + acc1.w);

    if (EPI == 0) {
        __nv_bfloat16 h[4], l[4];
        split2(acc.x, h[0], l[0]); split2(acc.y, h[1], l[1]);
        split2(acc.z, h[2], l[2]); split2(acc.w, h[3], l[3]);
        size_t go = (size_t)gid * (LD4 * 4) + t * 4;
        *reinterpret_cast<uint2*>(outH + go) = *reinterpret_cast<uint2*>(h);
        *reinterpret_cast<uint2*>(outL + go) = *reinterpret_cast<uint2*>(l);
    } else if (EPI == 1) {
        int c0 = t * 4;
        float a[4] = {acc.x, acc.y, acc.z, acc.w};
        __nv_bfloat16 h[4], l[4];
#pragma unroll
        for (int i = 0; i < 4; i++) {
            float sc = rsqrtf(var[c0 + i] + EPSV) * gam[c0 + i];
            float of = (bb[c0 + i] - mean[c0 + i]) * sc + bet[c0 + i];
            float vv = fmaxf(a[i] * sc + of, 0.f);
            split2(vv, h[i], l[i]);
        }
        size_t go = (size_t)gid * HH + c0;
        *reinterpret_cast<uint2*>(outH + go) = *reinterpret_cast<uint2*>(h);
        *reinterpret_cast<uint2*>(outL + go) = *reinterpret_cast<uint2*>(l);
    } else {
        int c0 = t * 4;
        float4 b4 = *reinterpret_cast<const float4*>(bb + c0);
        acc.x += b4.x; acc.y += b4.y; acc.z += b4.z; acc.w += b4.w;
        *reinterpret_cast<float4*>(outF + (size_t)gid * outw + c0) = acc;
    }
}

// ---------------- mma.sync split-bf16 GEMM ----------------
// EPI 0: outTmp = val (outw-wide)
// EPI 1: BN(val + bias) -> ReLU -> bf16 split -> outH/outL (256-wide)
template <int K_TOT, int NTILE, int EPI>
__global__ void __launch_bounds__(256)
k_gemm(const __nv_bfloat16* __restrict__ Ah, const __nv_bfloat16* __restrict__ Al,
       const __nv_bfloat16* __restrict__ Bh, const __nv_bfloat16* __restrict__ Bl,
       float* __restrict__ outTmp, int outw,
       __nv_bfloat16* __restrict__ outH, __nv_bfloat16* __restrict__ outL,
       const float* __restrict__ bb, const float* __restrict__ gam,
       const float* __restrict__ bet, const float* __restrict__ mean,
       const float* __restrict__ var) {
    constexpr int KC    = 32;
    constexpr int NCH   = K_TOT / KC;
    constexpr int SA    = 128 * 64;
    constexpr int SB    = NTILE * 64;
    constexpr int STAGE = 2 * SA + 2 * SB;
    constexpr int WM    = (NTILE == 128) ? 32 : 16;
    constexpr int WN    = (NTILE == 128) ? 64 : 32;
    constexpr int WARPS_N = NTILE / WN;
    constexpr int MT    = WM / 16;
    constexpr int NT    = WN / 8;

    extern __shared__ char smem[];
    const uint32_t sbase = smem_u32(smem);
    const int tid  = threadIdx.x;
    const int wid  = tid >> 5;
    const int lane = tid & 31;
    const int rowBase = blockIdx.y * 128;
    const int colBase = blockIdx.x * NTILE;
    const int warp_m  = wid / WARPS_N;
    const int warp_n  = wid % WARPS_N;

    float acc[MT][NT][4];
#pragma unroll
    for (int i = 0; i < MT; i++)
#pragma unroll
        for (int j = 0; j < NT; j++)
#pragma unroll
            for (int q = 0; q < 4; q++) acc[i][j][q] = 0.f;

    auto load_stage = [&](int s, int kc) {
        const uint32_t base = sbase + s * STAGE;
#pragma unroll
        for (int i = 0; i < 4; i++) {
            int u = tid + i * 256;
            int half = u >> 9;
            int v = u & 511;
            int r = v >> 2, c16 = v & 3;
            int grow = rowBase + r;
            const __nv_bfloat16* gp = (half ? Al : Ah);
            const __nv_bfloat16* srcp = gp + (size_t)(grow < NN ? grow : 0) * K_TOT + kc + c16 * 8;
            cp16(base + half * SA + swz(r, c16 * 16), srcp, (grow < NN) ? 16u : 0u);
        }
#pragma unroll
        for (int i = 0; i < (NTILE * 8) / 256; i++) {
            int u = tid + i * 256;
            int half = (u >= NTILE * 4) ? 1 : 0;
            int v = u - half * NTILE * 4;
            int r = v >> 2, c16 = v & 3;
            const __nv_bfloat16* gp = (half ? Bl : Bh);
            const __nv_bfloat16* srcp = gp + (size_t)(colBase + r) * K_TOT + kc + c16 * 8;
            cp16(base + 2 * SA + half * SB + swz(r, c16 * 16), srcp, 16u);
        }
    };

    load_stage(0, 0);
    CP_COMMIT();

    for (int ch = 0; ch < NCH; ch++) {
        if (ch + 1 < NCH) {
            load_stage((ch + 1) & 1, (ch + 1) * KC);
            CP_COMMIT();
            CP_WAIT(1);
        } else {
            CP_WAIT(0);
        }
        __syncthreads();

        const uint32_t base = sbase + (ch & 1) * STAGE;
#pragma unroll
        for (int ks = 0; ks < 2; ks++) {
            uint32_t ah[MT][4], al[MT][4];
            const int ab = ks * 32 + ((lane >> 4) << 4);
#pragma unroll
            for (int i = 0; i < MT; i++) {
                int r = warp_m * WM + i * 16 + (lane & 15);
                ldsm_x4(ah[i], base + swz(r, ab));
                ldsm_x4(al[i], base + SA + swz(r, ab));
            }
            const int bbyte = ks * 32 + ((lane >> 3) & 1) * 16;
#pragma unroll
            for (int j = 0; j < NT; j++) {
                int r = warp_n * WN + j * 8 + (lane & 7);
                uint32_t bh[2], bl[2];
                ldsm_x2(bh, base + 2 * SA + swz(r, bbyte));
                ldsm_x2(bl, base + 2 * SA + SB + swz(r, bbyte));
#pragma unroll
                for (int i = 0; i < MT; i++) {
                    mma16816(acc[i][j], ah[i], bh);
                    mma16816(acc[i][j], ah[i], bl);
                    mma16816(acc[i][j], al[i], bh);
                }
            }
        }
        __syncthreads();
    }

    const int g  = lane >> 2;
    const int tg = lane & 3;
#pragma unroll
    for (int i = 0; i < MT; i++) {
        int r0 = rowBase + warp_m * WM + i * 16 + g;
        int r1 = r0 + 8;
        bool v0 = r0 < NN, v1 = r1 < NN;
        if (EPI == 0) {
#pragma unroll
            for (int j = 0; j < NT; j++) {
                int col = colBase + warp_n * WN + j * 8 + 2 * tg;
                if (col >= outw) continue;
                if (v0) {
                    float2 tv = make_float2(acc[i][j][0], acc[i][j][1]);
                    *reinterpret_cast<float2*>(outTmp + (size_t)r0 * outw + col) = tv;
                }
                if (v1) {
                    float2 tv = make_float2(acc[i][j][2], acc[i][j][3]);
                    *reinterpret_cast<float2*>(outTmp + (size_t)r1 * outw + col) = tv;
                }
            }
        } else {
#pragma unroll
            for (int j = 0; j < NT; j++) {
                int col = colBase + warp_n * WN + j * 8 + 2 * tg;
                float sc0 = rsqrtf(var[col] + EPSV) * gam[col];
                float of0 = (bb[col] - mean[col]) * sc0 + bet[col];
                float sc1 = rsqrtf(var[col + 1] + EPSV) * gam[col + 1];
                float of1 = (bb[col + 1] - mean[col + 1]) * sc1 + bet[col + 1];
                if (v0) {
                    float x0 = fmaxf(acc[i][j][0] * sc0 + of0, 0.f);
                    float x1 = fmaxf(acc[i][j][1] * sc1 + of1, 0.f);
                    __nv_bfloat16 h[2], l[2];
                    split2(x0, h[0], l[0]); split2(x1, h[1], l[1]);
                    *reinterpret_cast<uint32_t*>(outH + (size_t)r0 * HH + col) = *reinterpret_cast<uint32_t*>(h);
                    *reinterpret_cast<uint32_t*>(outL + (size_t)r0 * HH + col) = *reinterpret_cast<uint32_t*>(l);
                }
                if (v1) {
                    float x0 = fmaxf(acc[i][j][2] * sc0 + of0, 0.f);
                    float x1 = fmaxf(acc[i][j][3] * sc1 + of1, 0.f);
                    __nv_bfloat16 h[2], l[2];
                    split2(x0, h[0], l[0]); split2(x1, h[1], l[1]);
                    *reinterpret_cast<uint32_t*>(outH + (size_t)r1 * HH + col) = *reinterpret_cast<uint32_t*>(h);
                    *reinterpret_cast<uint32_t*>(outL + (size_t)r1 * HH + col) = *reinterpret_cast<uint32_t*>(l);
                }
            }
        }
    }
}

// ---------------- launcher ----------------
extern "C" void kernel_launch(void* const* d_in, const int* in_sizes, int n_in,
                              void* d_out, int out_size) {
    const float* x     = (const float*)d_in[0];
    const int*   ei    = (const int*)  d_in[1];
    const float* W0    = (const float*)d_in[2];
    const float* b0    = (const float*)d_in[3];
    const float* W1    = (const float*)d_in[4];
    const float* b1    = (const float*)d_in[5];
    const float* W2    = (const float*)d_in[6];
    const float* b2    = (const float*)d_in[7];
    const float* W3    = (const float*)d_in[8];
    const float* b3    = (const float*)d_in[9];
    const float* gamma = (const float*)d_in[10];
    const float* beta  = (const float*)d_in[11];
    const float* mean  = (const float*)d_in[12];
    const float* var   = (const float*)d_in[13];
    float* out = (float*)d_out;
    const int* src = ei;
    const int* dst = ei + EE;

    float* tmpP;
    __nv_bfloat16 *ahP, *alP, *axhP, *axlP;
    __nv_bfloat16 *w0h, *w0l, *w1h, *w1l, *w2h, *w2l, *w3h, *w3l;
    cudaGetSymbolAddress((void**)&tmpP, g_tmp);
    cudaGetSymbolAddress((void**)&ahP,  g_ah);
    cudaGetSymbolAddress((void**)&alP,  g_al);
    cudaGetSymbolAddress((void**)&axhP, g_axh);
    cudaGetSymbolAddress((void**)&axlP, g_axl);
    cudaGetSymbolAddress((void**)&w0h, g_w0h); cudaGetSymbolAddress((void**)&w0l, g_w0l);
    cudaGetSymbolAddress((void**)&w1h, g_w1h); cudaGetSymbolAddress((void**)&w1l, g_w1l);
    cudaGetSymbolAddress((void**)&w2h, g_w2h); cudaGetSymbolAddress((void**)&w2l, g_w2l);
    cudaGetSymbolAddress((void**)&w3h, g_w3h); cudaGetSymbolAddress((void**)&w3l, g_w3l);

    const int SM128 = 2 * (2 * 8192 + 2 * 128 * 64);   // 65536
    const int SM32  = 2 * (2 * 8192 + 2 * 32 * 64);    // 40960
    cudaFuncSetAttribute(k_gemm<128, 128, 1>, cudaFuncAttributeMaxDynamicSharedMemorySize, SM128);
    cudaFuncSetAttribute(k_gemm<256, 128, 0>, cudaFuncAttributeMaxDynamicSharedMemorySize, SM128);
    cudaFuncSetAttribute(k_gemm<256, 32, 0>,  cudaFuncAttributeMaxDynamicSharedMemorySize, SM32);

    const int T = 256;
    // CSR build
    k_zero_cnt<<<(NN + T - 1) / T, T>>>();
    k_count   <<<(EE + T - 1) / T, T>>>(dst);
    k_scan    <<<1, 1024>>>();
    k_fill    <<<(EE + T - 1) / T, T>>>(src, dst);
    // weights: transpose + split (+pad for W3)
    k_wsplit<<<(HH * DIN + T - 1) / T, T>>>(W0, w0h, w0l, DIN, HH, HH);
    k_wsplit<<<(HH * HH  + T - 1) / T, T>>>(W1, w1h, w1l, HH, HH, HH);
    k_wsplit<<<(HH * HH  + T - 1) / T, T>>>(W2, w2h, w2l, HH, HH, HH);
    k_wsplit<<<(OUTP * HH + T - 1) / T, T>>>(W3, w3h, w3l, HH, OUTD, OUTP);

    // ---- layer 0: aggregate x (128 cols) with fused bf16 split, then GEMM+BN+ReLU+split
    k_gather<32, 32, 0><<<(NN * 32 + 255) / 256, 256>>>(x, axhP, axlP,
        nullptr, 0, nullptr, nullptr, nullptr, nullptr, nullptr);
    k_gemm<128, 128, 1><<<dim3(2, NBLK), 256, SM128>>>(axhP, axlP, w0h, w0l,
        nullptr, 0, ahP, alP, b0, gamma, beta, mean, var);

    // ---- layer 1
    k_gemm<256, 128, 0><<<dim3(2, NBLK), 256, SM128>>>(ahP, alP, w1h, w1l,
        tmpP, HH, nullptr, nullptr, nullptr, nullptr, nullptr, nullptr, nullptr);
    k_gather<64, 64, 1><<<(NN * 64 + 255) / 256, 256>>>(tmpP, ahP, alP,
        nullptr, 0, b1, gamma + HH, beta + HH, mean + HH, var + HH);

    // ---- layer 2
    k_gemm<256, 128, 0><<<dim3(2, NBLK), 256, SM128>>>(ahP, alP, w2h, w2l,
        tmpP, HH, nullptr, nullptr, nullptr, nullptr, nullptr, nullptr, nullptr);
    k_gather<64, 64, 1><<<(NN * 64 + 255) / 256, 256>>>(tmpP, ahP, alP,
        nullptr, 0, b2, gamma + 2 * HH, beta + 2 * HH, mean + 2 * HH, var + 2 * HH);

    // ---- layer 3: GEMM (20-wide out), aggregate + bias -> out
    k_gemm<256, 32, 0><<<dim3(1, NBLK), 256, SM32>>>(ahP, alP, w3h, w3l,
        tmpP, OUTD, nullptr, nullptr, nullptr, nullptr, nullptr, nullptr, nullptr);
    k_gather<5, 8, 2><<<(NN * 8 + 255) / 256, 256>>>(tmpP, nullptr, nullptr,
        out, OUTD, b3, nullptr, nullptr, nullptr, nullptr);
}